// round 6
// baseline (speedup 1.0000x reference)
#include <cuda_runtime.h>
#include <cuda_bf16.h>
#include <cstdint>

#define BB 4
#define NN 50000
#define EE 800000

// ---------------------------------------------------------------------------
// Scratch (static device globals; runtime allocation forbidden)
// ---------------------------------------------------------------------------
__device__ float4 g_ya4[BB * NN * 8];     // ya = x@W1[0:32]+b1, node-major (n*BB+b)
__device__ float4 g_yb4[BB * NN * 8];     // yb = x@W1[32:64]
__device__ float4 g_h2[EE * BB * 8];      // per-(edge,batch) h2 rows (32 floats)
__device__ int    g_deg[NN];
__device__ int    g_off[NN + 1];
__device__ int    g_cur[NN];
__device__ int    g_list[2 * EE];         // entry = (edge<<1) | role(1=tgt/+,0=src/-)
__device__ float  g_part[512];
__device__ float  g_stat[2];              // mean, rstd
__device__ int    g_is64;

typedef unsigned long long u64;

// ---- packed f32x2 helpers (sm_103a FFMA2 path; PTX-only) ----
__device__ __forceinline__ u64 pk2(float lo, float hi) {
    u64 r; asm("mov.b64 %0,{%1,%2};" : "=l"(r) : "f"(lo), "f"(hi)); return r;
}
__device__ __forceinline__ void upk2(float& lo, float& hi, u64 v) {
    asm("mov.b64 {%0,%1},%2;" : "=f"(lo), "=f"(hi) : "l"(v));
}
__device__ __forceinline__ u64 fma2(u64 a, u64 b, u64 c) {
    u64 d; asm("fma.rn.f32x2 %0,%1,%2,%3;" : "=l"(d) : "l"(a), "l"(b), "l"(c)); return d;
}
__device__ __forceinline__ u64 add2(u64 a, u64 b) {
    u64 d; asm("add.rn.f32x2 %0,%1,%2;" : "=l"(d) : "l"(a), "l"(b)); return d;
}

__device__ __forceinline__ float sigf(float x) {
    return __fdividef(1.0f, 1.0f + __expf(-x));
}

// ---------------------------------------------------------------------------
// 0. init: zero degree counters; thread 0 of block 0 detects index width
// ---------------------------------------------------------------------------
__global__ void k_init(const void* ei) {
    int i = blockIdx.x * blockDim.x + threadIdx.x;
    if (i < NN) g_deg[i] = 0;
    if (i == 0) {
        const long long* p = (const long long*)ei;
        int ok64 = 1;
        for (int j = 0; j < 16; j++) {
            long long v = p[j];
            if (v < 0 || v >= (long long)NN) ok64 = 0;
        }
        g_is64 = ok64;
    }
}

__device__ __forceinline__ void load_edge(const void* ei, int e, int& src, int& tgt) {
    if (g_is64) {
        const long long* p = (const long long*)ei;
        src = (int)__ldg(&p[e]);
        tgt = (int)__ldg(&p[EE + e]);
    } else {
        const int* p = (const int*)ei;
        src = __ldg(&p[e]);
        tgt = __ldg(&p[EE + e]);
    }
    src = min(max(src, 0), NN - 1);
    tgt = min(max(tgt, 0), NN - 1);
}

// ---------------------------------------------------------------------------
// 1. edge_attr stats (two-pass deterministic)
// ---------------------------------------------------------------------------
__global__ void k_stat1(const float* __restrict__ ea) {
    __shared__ float ss[256], sq[256];
    int tid = threadIdx.x;
    float s = 0.f, q = 0.f;
    for (int i = blockIdx.x * 256 + tid; i < EE; i += 256 * 256) {
        float v = __ldg(&ea[i]);
        s += v; q += v * v;
    }
    ss[tid] = s; sq[tid] = q;
    __syncthreads();
    for (int o = 128; o > 0; o >>= 1) {
        if (tid < o) { ss[tid] += ss[tid + o]; sq[tid] += sq[tid + o]; }
        __syncthreads();
    }
    if (tid == 0) {
        g_part[blockIdx.x]       = ss[0];
        g_part[256 + blockIdx.x] = sq[0];
    }
}

__global__ void k_stat2() {
    __shared__ float ss[256], sq[256];
    int tid = threadIdx.x;
    ss[tid] = g_part[tid];
    sq[tid] = g_part[256 + tid];
    __syncthreads();
    for (int o = 128; o > 0; o >>= 1) {
        if (tid < o) { ss[tid] += ss[tid + o]; sq[tid] += sq[tid + o]; }
        __syncthreads();
    }
    if (tid == 0) {
        float s = ss[0], q = sq[0];
        g_stat[0] = s / (float)EE;
        g_stat[1] = rsqrtf((q - s * s / (float)EE) / (float)(EE - 1));
    }
}

// ---------------------------------------------------------------------------
// 2. CSR build: count -> scan -> fill
// ---------------------------------------------------------------------------
__global__ void k_count(const void* __restrict__ ei) {
    int e = blockIdx.x * blockDim.x + threadIdx.x;
    if (e >= EE) return;
    int src, tgt;
    load_edge(ei, e, src, tgt);
    atomicAdd(&g_deg[src], 1);
    atomicAdd(&g_deg[tgt], 1);
}

#define SCAN_CHUNK 49   // 49 * 1024 = 50176 >= NN
__global__ void __launch_bounds__(1024) k_scan() {
    __shared__ int part[1024];
    int tid = threadIdx.x;
    int lo = tid * SCAN_CHUNK;
    int hi = min(lo + SCAN_CHUNK, NN);
    int s = 0;
    for (int i = lo; i < hi; i++) s += g_deg[i];
    part[tid] = s;
    __syncthreads();
    for (int o = 1; o < 1024; o <<= 1) {
        int v = (tid >= o) ? part[tid - o] : 0;
        __syncthreads();
        part[tid] += v;
        __syncthreads();
    }
    int run = (tid == 0) ? 0 : part[tid - 1];
    for (int i = lo; i < hi; i++) {
        g_off[i] = run;
        g_cur[i] = run;
        run += g_deg[i];
    }
    if (tid == 1023) g_off[NN] = part[1023];
}

__global__ void k_fill(const void* __restrict__ ei) {
    int e = blockIdx.x * blockDim.x + threadIdx.x;
    if (e >= EE) return;
    int src, tgt;
    load_edge(ei, e, src, tgt);
    int p0 = atomicAdd(&g_cur[src], 1);
    g_list[p0] = (e << 1);          // src role: minus
    int p1 = atomicAdd(&g_cur[tgt], 1);
    g_list[p1] = (e << 1) | 1;      // tgt role: plus
}

// ---------------------------------------------------------------------------
// 3. precompute ya/yb, node-major (n*BB+b)
// ---------------------------------------------------------------------------
__global__ void __launch_bounds__(256) k_pre(const float* __restrict__ x,
                                             const float* __restrict__ W1,
                                             const float* __restrict__ b1) {
    int lane   = threadIdx.x & 31;
    int warp   = (blockIdx.x * blockDim.x + threadIdx.x) >> 5;
    int nwarps = (gridDim.x * blockDim.x) >> 5;

    u64 wab[32];
#pragma unroll
    for (int k = 0; k < 32; k++) {
        wab[k] = pk2(__ldg(&W1[k * 32 + lane]), __ldg(&W1[(32 + k) * 32 + lane]));
    }
    u64 binit = pk2(__ldg(&b1[lane]), 0.f);

    float* ya = reinterpret_cast<float*>(g_ya4);
    float* yb = reinterpret_cast<float*>(g_yb4);

    for (int row = warp; row < BB * NN; row += nwarps) {
        int b = row / NN;
        int n = row - b * NN;
        float xv = __ldg(&x[row * 32 + lane]);
        u64 acc = binit;
#pragma unroll
        for (int k = 0; k < 32; k++) {
            float xk = __shfl_sync(0xffffffffu, xv, k);
            acc = fma2(pk2(xk, xk), wab[k], acc);
        }
        float sa, sb;
        upk2(sa, sb, acc);
        int off = (n * BB + b) * 32 + lane;
        ya[off] = sa;
        yb[off] = sb;
    }
}

// ---------------------------------------------------------------------------
// 4. edge kernel: warp=edge, lane=(b=lane>>3, f4=lane&7). Stores h2 rows
//    (no atomics): 512B contiguous STG.128 per warp.
// ---------------------------------------------------------------------------
__global__ void __launch_bounds__(256) k_edge(const void* __restrict__ ei,
                                              const float* __restrict__ ea,
                                              const float* __restrict__ W1,
                                              const float* __restrict__ W2,
                                              const float* __restrict__ b2) {
    __shared__ ulonglong2 w1cp[8];
    __shared__ ulonglong2 b2p[8];
    __shared__ ulonglong2 w2p[32][8];

    int tid = threadIdx.x;
    for (int i = tid; i < 32 * 32; i += 256) {
        int k = i >> 5, j = i & 31;
        reinterpret_cast<float*>(w2p)[k * 32 + j] = (j < 30) ? W2[k * 30 + j] : 0.f;
    }
    if (tid < 32) {
        reinterpret_cast<float*>(w1cp)[tid] = W1[64 * 32 + tid];
        reinterpret_cast<float*>(b2p)[tid]  = (tid < 30) ? b2[tid] : 0.f;
    }
    __syncthreads();

    int e = (blockIdx.x * 256 + tid) >> 5;
    if (e >= EE) return;
    int lane = tid & 31;
    int f4   = lane & 7;

    int src, tgt;
    load_edge(ei, e, src, tgt);

    float ean = (__ldg(&ea[e]) - g_stat[0]) * g_stat[1];
    u64 ean2 = pk2(ean, ean);

    const ulonglong2* pa = reinterpret_cast<const ulonglong2*>(g_ya4) + src * 32 + lane;
    const ulonglong2* pb = reinterpret_cast<const ulonglong2*>(g_yb4) + tgt * 32 + lane;
    ulonglong2 A = *pa;
    ulonglong2 C = *pb;

    ulonglong2 wc = w1cp[f4];
    u64 t0 = fma2(ean2, wc.x, add2(A.x, C.x));
    u64 t1 = fma2(ean2, wc.y, add2(A.y, C.y));

    float h1v[4];
    {
        float v0, v1, v2, v3;
        upk2(v0, v1, t0);
        upk2(v2, v3, t1);
        h1v[0] = sigf(v0); h1v[1] = sigf(v1);
        h1v[2] = sigf(v2); h1v[3] = sigf(v3);
    }

    ulonglong2 binit = b2p[f4];
    u64 acc0 = binit.x, acc1 = binit.y;
#pragma unroll
    for (int k = 0; k < 32; k++) {
        float h = __shfl_sync(0xffffffffu, h1v[k & 3], k >> 2, 8);
        u64 hh = pk2(h, h);
        ulonglong2 w = w2p[k][f4];
        acc0 = fma2(hh, w.x, acc0);
        acc1 = fma2(hh, w.y, acc1);
    }

    float s0, s1, s2, s3;
    upk2(s0, s1, acc0);
    upk2(s2, s3, acc1);
    s0 = sigf(s0); s1 = sigf(s1);
    if (f4 == 7) { s2 = 0.f; s3 = 0.f; }
    else         { s2 = sigf(s2); s3 = sigf(s3); }

    // store: warp covers 512B contiguous
    float4* dst = g_h2 + (size_t)e * 32 + lane;   // (e, b, f4) quads
    *dst = make_float4(s0, s1, s2, s3);
}

// ---------------------------------------------------------------------------
// 5. gather kernel: warp = node, lanes (b, f4). Sums signed h2 rows of all
//    incident edges, then applies W3 + b3 + sigmoid in-warp and stores out.
// ---------------------------------------------------------------------------
__global__ void __launch_bounds__(256) k_gather(const float* __restrict__ W3,
                                                const float* __restrict__ b3,
                                                float* __restrict__ out) {
    __shared__ ulonglong2 w3p[30][8];   // W3 row k: 32 floats = 8 x (2 pairs)
    __shared__ ulonglong2 b3p[8];

    int tid = threadIdx.x;
    for (int i = tid; i < 30 * 32; i += 256) {
        int k = i >> 5, j = i & 31;
        reinterpret_cast<float*>(w3p)[k * 32 + j] = W3[k * 32 + j];
    }
    if (tid < 32) reinterpret_cast<float*>(b3p)[tid] = b3[tid];
    __syncthreads();

    int n = (blockIdx.x * 256 + tid) >> 5;
    if (n >= NN) return;
    int lane = tid & 31;
    int b    = lane >> 3;
    int f4   = lane & 7;

    int beg = g_off[n];
    int end = g_off[n + 1];

    u64 a0 = 0, a1 = 0;   // accumulated features f4*4 .. f4*4+3
    const ulonglong2* h2base = reinterpret_cast<const ulonglong2*>(g_h2);
    for (int i = beg; i < end; i++) {
        int entry = g_list[i];
        int e     = entry >> 1;
        u64 m = (entry & 1) ? 0ull : 0x8000000080000000ull;  // src role: negate
        ulonglong2 v = __ldg(h2base + (size_t)e * 32 + lane);
        a0 = add2(a0, v.x ^ m);
        a1 = add2(a1, v.y ^ m);
    }

    // features of this (n,b) are spread across the 8-lane group; matvec @W3
    float av[4];
    upk2(av[0], av[1], a0);
    upk2(av[2], av[3], a1);

    ulonglong2 bi = b3p[f4];
    u64 o0 = bi.x, o1 = bi.y;
#pragma unroll
    for (int k = 0; k < 30; k++) {
        float h = __shfl_sync(0xffffffffu, av[k & 3], k >> 2, 8);
        u64 hh = pk2(h, h);
        ulonglong2 w = w3p[k][f4];
        o0 = fma2(hh, w.x, o0);
        o1 = fma2(hh, w.y, o1);
    }

    float r0, r1, r2, r3;
    upk2(r0, r1, o0);
    upk2(r2, r3, o1);
    float4* op = reinterpret_cast<float4*>(out) + (size_t)(b * NN + n) * 8 + f4;
    *op = make_float4(sigf(r0), sigf(r1), sigf(r2), sigf(r3));
}

// ---------------------------------------------------------------------------
// launch: resolve inputs by element count (robust to metadata ordering).
// ---------------------------------------------------------------------------
extern "C" void kernel_launch(void* const* d_in, const int* in_sizes, int n_in,
                              void* d_out, int out_size) {
    const float *x = 0, *ea = 0, *W1 = 0, *b1 = 0, *W2 = 0, *b2 = 0, *W3 = 0, *b3 = 0;
    const void* ei = 0;
    int nW = 0, nb = 0;
    for (int i = 0; i < n_in; i++) {
        switch (in_sizes[i]) {
            case 6400000: x  = (const float*)d_in[i]; break;
            case 1600000: ei = d_in[i];               break;
            case 800000:  ea = (const float*)d_in[i]; break;
            case 2080:    W1 = (const float*)d_in[i]; break;
            case 960:     if (nW++ == 0) W2 = (const float*)d_in[i];
                          else           W3 = (const float*)d_in[i]; break;
            case 32:      if (nb++ == 0) b1 = (const float*)d_in[i];
                          else           b3 = (const float*)d_in[i]; break;
            case 30:      b2 = (const float*)d_in[i]; break;
        }
    }
    float* out = (float*)d_out;

    k_init<<<(NN + 255) / 256, 256>>>(ei);
    k_stat1<<<256, 256>>>(ea);
    k_stat2<<<1, 256>>>();
    k_count<<<(EE + 255) / 256, 256>>>(ei);
    k_scan<<<1, 1024>>>();
    k_fill<<<(EE + 255) / 256, 256>>>(ei);
    k_pre<<<512, 256>>>(x, W1, b1);
    k_edge<<<(EE * 32 + 255) / 256, 256>>>(ei, ea, W1, W2, b2);
    k_gather<<<(NN * 32 + 255) / 256, 256>>>(W3, b3, out);
}

// round 8
// speedup vs baseline: 1.3235x; 1.3235x over previous
#include <cuda_runtime.h>
#include <cuda_bf16.h>
#include <cstdint>

#define BB 4
#define NN 50000
#define EE 800000

// ---------------------------------------------------------------------------
// Scratch. Node-major layout: row (n, b) at offset ((n*BB + b) * 32) floats,
// so one node's 4 batch rows are 512B contiguous (coalesced warp gathers).
// ---------------------------------------------------------------------------
__device__ float4 g_ya4[BB * NN * 8];   // ya = x@W1[0:32] + b1
__device__ float4 g_yb4[BB * NN * 8];   // yb = x@W1[32:64]
__device__ float4 g_acc4[BB * NN * 8];  // node accumulator (30 used, pad 32)
__device__ float  g_part[512];
__device__ float  g_stat[2];            // mean, rstd
__device__ int    g_is64;

typedef unsigned long long u64;

// ---- packed f32x2 helpers (sm_103a FFMA2 path; PTX-only) ----
__device__ __forceinline__ u64 pk2(float lo, float hi) {
    u64 r; asm("mov.b64 %0,{%1,%2};" : "=l"(r) : "f"(lo), "f"(hi)); return r;
}
__device__ __forceinline__ void upk2(float& lo, float& hi, u64 v) {
    asm("mov.b64 {%0,%1},%2;" : "=f"(lo), "=f"(hi) : "l"(v));
}
__device__ __forceinline__ u64 fma2(u64 a, u64 b, u64 c) {
    u64 d; asm("fma.rn.f32x2 %0,%1,%2,%3;" : "=l"(d) : "l"(a), "l"(b), "l"(c)); return d;
}
__device__ __forceinline__ u64 add2(u64 a, u64 b) {
    u64 d; asm("add.rn.f32x2 %0,%1,%2;" : "=l"(d) : "l"(a), "l"(b)); return d;
}

__device__ __forceinline__ float sigf(float x) {     // exact-ish sigmoid
    return __fdividef(1.0f, 1.0f + __expf(-x));
}
__device__ __forceinline__ float sigt(float x) {     // fast sigmoid via MUFU tanh
    float t;
    asm("tanh.approx.f32 %0, %1;" : "=f"(t) : "f"(x * 0.5f));
    return fmaf(0.5f, t, 0.5f);
}
__device__ __forceinline__ float negf(float x) {
    return __int_as_float(__float_as_int(x) ^ 0x80000000);
}
__device__ __forceinline__ void red4(float* p, float a, float b, float c, float d) {
    asm volatile("red.global.add.v4.f32 [%0], {%1,%2,%3,%4};"
                 :: "l"(p), "f"(a), "f"(b), "f"(c), "f"(d) : "memory");
}

__device__ __forceinline__ void load_edge(const void* ei, int e, int& src, int& tgt) {
    if (g_is64) {
        const long long* p = (const long long*)ei;
        src = (int)__ldg(&p[e]);
        tgt = (int)__ldg(&p[EE + e]);
    } else {
        const int* p = (const int*)ei;
        src = __ldg(&p[e]);
        tgt = __ldg(&p[EE + e]);
    }
    src = min(max(src, 0), NN - 1);
    tgt = min(max(tgt, 0), NN - 1);
}

// ---------------------------------------------------------------------------
// 0. stats pass 1 + index-width detection (fused; launch index 0)
// ---------------------------------------------------------------------------
__global__ void k_stat1(const float* __restrict__ ea, const void* __restrict__ ei) {
    if (blockIdx.x == 0 && threadIdx.x == 0) {
        const long long* p = (const long long*)ei;
        int ok64 = 1;
        for (int j = 0; j < 16; j++) {
            long long v = p[j];
            if (v < 0 || v >= (long long)NN) ok64 = 0;
        }
        g_is64 = ok64;
    }
    __shared__ float ss[256], sq[256];
    int tid = threadIdx.x;
    float s = 0.f, q = 0.f;
    for (int i = blockIdx.x * 256 + tid; i < EE; i += 256 * 256) {
        float v = __ldg(&ea[i]);
        s += v; q += v * v;
    }
    ss[tid] = s; sq[tid] = q;
    __syncthreads();
    for (int o = 128; o > 0; o >>= 1) {
        if (tid < o) { ss[tid] += ss[tid + o]; sq[tid] += sq[tid + o]; }
        __syncthreads();
    }
    if (tid == 0) {
        g_part[blockIdx.x]       = ss[0];
        g_part[256 + blockIdx.x] = sq[0];
    }
}

// 1. combine partials -> mean, rstd (ddof=1)
__global__ void k_stat2() {
    __shared__ float ss[256], sq[256];
    int tid = threadIdx.x;
    ss[tid] = g_part[tid];
    sq[tid] = g_part[256 + tid];
    __syncthreads();
    for (int o = 128; o > 0; o >>= 1) {
        if (tid < o) { ss[tid] += ss[tid + o]; sq[tid] += sq[tid + o]; }
        __syncthreads();
    }
    if (tid == 0) {
        float s = ss[0], q = sq[0];
        g_stat[0] = s / (float)EE;
        g_stat[1] = rsqrtf((q - s * s / (float)EE) / (float)(EE - 1));
    }
}

// ---------------------------------------------------------------------------
// 2. prez: zero accumulator + precompute ya/yb (node-major), fused
// ---------------------------------------------------------------------------
__global__ void __launch_bounds__(256) k_prez(const float* __restrict__ x,
                                              const float* __restrict__ W1,
                                              const float* __restrict__ b1) {
    // zero g_acc4 (different buffer than ya/yb; no intra-kernel ordering needed)
    int gt = blockIdx.x * blockDim.x + threadIdx.x;
    for (int i = gt; i < BB * NN * 8; i += gridDim.x * blockDim.x)
        g_acc4[i] = make_float4(0.f, 0.f, 0.f, 0.f);

    int lane   = threadIdx.x & 31;
    int warp   = gt >> 5;
    int nwarps = (gridDim.x * blockDim.x) >> 5;

    u64 wab[32];
#pragma unroll
    for (int k = 0; k < 32; k++) {
        wab[k] = pk2(__ldg(&W1[k * 32 + lane]), __ldg(&W1[(32 + k) * 32 + lane]));
    }
    u64 binit = pk2(__ldg(&b1[lane]), 0.f);

    float* ya = reinterpret_cast<float*>(g_ya4);
    float* yb = reinterpret_cast<float*>(g_yb4);

    for (int row = warp; row < BB * NN; row += nwarps) {
        int b = row / NN;
        int n = row - b * NN;
        float xv = __ldg(&x[row * 32 + lane]);
        u64 acc = binit;
#pragma unroll
        for (int k = 0; k < 32; k++) {
            float xk = __shfl_sync(0xffffffffu, xv, k);
            acc = fma2(pk2(xk, xk), wab[k], acc);
        }
        float sa, sb;
        upk2(sa, sb, acc);
        int off = (n * BB + b) * 32 + lane;
        ya[off] = sa;
        yb[off] = sb;
    }
}

// ---------------------------------------------------------------------------
// 3. main edge kernel (LAUNCH INDEX 3 -> ncu captures this one).
//    WARP = edge; lane = (b = lane>>3, f4 = lane&7). Coalesced gathers+REDs.
// ---------------------------------------------------------------------------
__global__ void __launch_bounds__(256) k_edge(const void* __restrict__ ei,
                                              const float* __restrict__ ea,
                                              const float* __restrict__ W1,
                                              const float* __restrict__ W2,
                                              const float* __restrict__ b2) {
    __shared__ ulonglong2 w1cp[8];     // W1 edge-attr row as 8 x (2 pairs)
    __shared__ ulonglong2 b2p[8];      // b2 padded, pairs
    __shared__ ulonglong2 w2p[32][8];  // W2[k] padded to 32 floats = 8 x 16B

    int tid = threadIdx.x;
    for (int i = tid; i < 32 * 32; i += 256) {
        int k = i >> 5, j = i & 31;
        reinterpret_cast<float*>(w2p)[k * 32 + j] = (j < 30) ? W2[k * 30 + j] : 0.f;
    }
    if (tid < 32) {
        reinterpret_cast<float*>(w1cp)[tid] = W1[64 * 32 + tid];
        reinterpret_cast<float*>(b2p)[tid]  = (tid < 30) ? b2[tid] : 0.f;
    }
    __syncthreads();

    int e = (blockIdx.x * 256 + tid) >> 5;     // warp id = edge
    if (e >= EE) return;
    int lane = tid & 31;
    int f4   = lane & 7;

    int src, tgt;
    load_edge(ei, e, src, tgt);

    float ean = (__ldg(&ea[e]) - g_stat[0]) * g_stat[1];
    u64 ean2 = pk2(ean, ean);

    // gather: lane reads its 16B chunk; warp covers 512B contiguous per side
    const ulonglong2* pa = reinterpret_cast<const ulonglong2*>(g_ya4) + src * 32 + lane;
    const ulonglong2* pb = reinterpret_cast<const ulonglong2*>(g_yb4) + tgt * 32 + lane;
    ulonglong2 A = *pa;
    ulonglong2 C = *pb;

    ulonglong2 wc = w1cp[f4];
    u64 t0 = fma2(ean2, wc.x, add2(A.x, C.x));
    u64 t1 = fma2(ean2, wc.y, add2(A.y, C.y));

    float h1v[4];
    {
        float v0, v1, v2, v3;
        upk2(v0, v1, t0);
        upk2(v2, v3, t1);
        // fast sigmoid OK here: error attenuated by layer 2 + output sigmoid
        h1v[0] = sigt(v0); h1v[1] = sigt(v1);
        h1v[2] = sigt(v2); h1v[3] = sigt(v3);
    }

    // layer 2: lane owns outputs j = f4*4 .. f4*4+3
    ulonglong2 binit = b2p[f4];
    u64 acc0 = binit.x, acc1 = binit.y;
#pragma unroll
    for (int k = 0; k < 32; k++) {
        float h = __shfl_sync(0xffffffffu, h1v[k & 3], k >> 2, 8);  // batch-group bcast
        u64 hh = pk2(h, h);
        ulonglong2 w = w2p[k][f4];
        acc0 = fma2(hh, w.x, acc0);
        acc1 = fma2(hh, w.y, acc1);
    }

    float s0, s1, s2, s3;
    upk2(s0, s1, acc0);
    upk2(s2, s3, acc1);
    s0 = sigf(s0); s1 = sigf(s1);
    if (f4 == 7) { s2 = 0.f; s3 = 0.f; }      // outputs 30,31 are padding
    else         { s2 = sigf(s2); s3 = sigf(s3); }

    // scatter: warp writes 512B contiguous per side
    float* at = reinterpret_cast<float*>(g_acc4) + tgt * 128 + lane * 4;
    float* as = reinterpret_cast<float*>(g_acc4) + src * 128 + lane * 4;
    red4(at, s0, s1, s2, s3);
    red4(as, negf(s0), negf(s1), negf(s2), negf(s3));
}

// ---------------------------------------------------------------------------
// 4. final: out = sigmoid(acc[:, :30] @ W3 + b3)   (warp per output row)
// ---------------------------------------------------------------------------
__global__ void __launch_bounds__(256) k_out(const float* __restrict__ W3,
                                             const float* __restrict__ b3,
                                             float* __restrict__ out) {
    int lane   = threadIdx.x & 31;
    int warp   = (blockIdx.x * blockDim.x + threadIdx.x) >> 5;
    int nwarps = (gridDim.x * blockDim.x) >> 5;

    float w3r[30];
#pragma unroll
    for (int k = 0; k < 30; k++) w3r[k] = __ldg(&W3[k * 32 + lane]);
    float bv = __ldg(&b3[lane]);

    const float* accf = reinterpret_cast<const float*>(g_acc4);

    for (int row = warp; row < BB * NN; row += nwarps) {
        int b = row / NN;
        int n = row - b * NN;
        float av = accf[(n * BB + b) * 32 + lane];
        float s = bv;
#pragma unroll
        for (int k = 0; k < 30; k++) {
            s = fmaf(__shfl_sync(0xffffffffu, av, k), w3r[k], s);
        }
        out[row * 32 + lane] = sigf(s);
    }
}

// ---------------------------------------------------------------------------
// launch: resolve inputs by element count (robust to metadata ordering).
// Launch order chosen so k_edge is at index 3 (= ncu capture slot).
// ---------------------------------------------------------------------------
extern "C" void kernel_launch(void* const* d_in, const int* in_sizes, int n_in,
                              void* d_out, int out_size) {
    const float *x = 0, *ea = 0, *W1 = 0, *b1 = 0, *W2 = 0, *b2 = 0, *W3 = 0, *b3 = 0;
    const void* ei = 0;
    int nW = 0, nb = 0;
    for (int i = 0; i < n_in; i++) {
        switch (in_sizes[i]) {
            case 6400000: x  = (const float*)d_in[i]; break;
            case 1600000: ei = d_in[i];               break;
            case 800000:  ea = (const float*)d_in[i]; break;
            case 2080:    W1 = (const float*)d_in[i]; break;
            case 960:     if (nW++ == 0) W2 = (const float*)d_in[i];
                          else           W3 = (const float*)d_in[i]; break;
            case 32:      if (nb++ == 0) b1 = (const float*)d_in[i];
                          else           b3 = (const float*)d_in[i]; break;
            case 30:      b2 = (const float*)d_in[i]; break;
        }
    }
    float* out = (float*)d_out;

    k_stat1<<<256, 256>>>(ea, ei);                 // 0
    k_stat2<<<1, 256>>>();                         // 1
    k_prez<<<512, 256>>>(x, W1, b1);               // 2
    k_edge<<<(EE * 32 + 255) / 256, 256>>>(ei, ea, W1, W2, b2);   // 3  <- profiled
    k_out<<<512, 256>>>(W3, b3, out);              // 4
}

// round 9
// speedup vs baseline: 2.0637x; 1.5592x over previous
#include <cuda_runtime.h>
#include <cuda_bf16.h>
#include <cstdint>

#define BB 4
#define NN 50000
#define EE 800000
#define TILE_E 64          // edges per CTA
#define ROWF 36            // tile row stride in floats (144B: 16B-aligned, conflict-free)

// ---------------------------------------------------------------------------
// Scratch. Node-major: row (n, b) at ((n*BB + b) * 32) floats.
// ---------------------------------------------------------------------------
__device__ float4 g_ya4[BB * NN * 8];
__device__ float4 g_yb4[BB * NN * 8];
__device__ float4 g_acc4[BB * NN * 8];
__device__ float  g_part[512];
__device__ float  g_stat[2];
__device__ int    g_is64;

typedef unsigned long long u64;

__device__ __forceinline__ u64 pk2(float lo, float hi) {
    u64 r; asm("mov.b64 %0,{%1,%2};" : "=l"(r) : "f"(lo), "f"(hi)); return r;
}
__device__ __forceinline__ void upk2(float& lo, float& hi, u64 v) {
    asm("mov.b64 {%0,%1},%2;" : "=f"(lo), "=f"(hi) : "l"(v));
}
__device__ __forceinline__ u64 fma2(u64 a, u64 b, u64 c) {
    u64 d; asm("fma.rn.f32x2 %0,%1,%2,%3;" : "=l"(d) : "l"(a), "l"(b), "l"(c)); return d;
}
__device__ __forceinline__ u64 add2(u64 a, u64 b) {
    u64 d; asm("add.rn.f32x2 %0,%1,%2;" : "=l"(d) : "l"(a), "l"(b)); return d;
}

__device__ __forceinline__ float sigf(float x) {
    return __fdividef(1.0f, 1.0f + __expf(-x));
}
__device__ __forceinline__ float sigt(float x) {     // fast sigmoid (h1 only)
    float t;
    asm("tanh.approx.f32 %0, %1;" : "=f"(t) : "f"(x * 0.5f));
    return fmaf(0.5f, t, 0.5f);
}
__device__ __forceinline__ float negf(float x) {
    return __int_as_float(__float_as_int(x) ^ 0x80000000);
}
__device__ __forceinline__ void red4(float* p, float a, float b, float c, float d) {
    asm volatile("red.global.add.v4.f32 [%0], {%1,%2,%3,%4};"
                 :: "l"(p), "f"(a), "f"(b), "f"(c), "f"(d) : "memory");
}

__device__ __forceinline__ void load_edge(const void* ei, int e, int& src, int& tgt) {
    if (g_is64) {
        const long long* p = (const long long*)ei;
        src = (int)__ldg(&p[e]);
        tgt = (int)__ldg(&p[EE + e]);
    } else {
        const int* p = (const int*)ei;
        src = __ldg(&p[e]);
        tgt = __ldg(&p[EE + e]);
    }
    src = min(max(src, 0), NN - 1);
    tgt = min(max(tgt, 0), NN - 1);
}

// ---------------------------------------------------------------------------
// 0. stats pass 1 + index-width detection
// ---------------------------------------------------------------------------
__global__ void k_stat1(const float* __restrict__ ea, const void* __restrict__ ei) {
    if (blockIdx.x == 0 && threadIdx.x == 0) {
        const long long* p = (const long long*)ei;
        int ok64 = 1;
        for (int j = 0; j < 16; j++) {
            long long v = p[j];
            if (v < 0 || v >= (long long)NN) ok64 = 0;
        }
        g_is64 = ok64;
    }
    __shared__ float ss[256], sq[256];
    int tid = threadIdx.x;
    float s = 0.f, q = 0.f;
    for (int i = blockIdx.x * 256 + tid; i < EE; i += 256 * 256) {
        float v = __ldg(&ea[i]);
        s += v; q += v * v;
    }
    ss[tid] = s; sq[tid] = q;
    __syncthreads();
    for (int o = 128; o > 0; o >>= 1) {
        if (tid < o) { ss[tid] += ss[tid + o]; sq[tid] += sq[tid + o]; }
        __syncthreads();
    }
    if (tid == 0) {
        g_part[blockIdx.x]       = ss[0];
        g_part[256 + blockIdx.x] = sq[0];
    }
}

__global__ void k_stat2() {
    __shared__ float ss[256], sq[256];
    int tid = threadIdx.x;
    ss[tid] = g_part[tid];
    sq[tid] = g_part[256 + tid];
    __syncthreads();
    for (int o = 128; o > 0; o >>= 1) {
        if (tid < o) { ss[tid] += ss[tid + o]; sq[tid] += sq[tid + o]; }
        __syncthreads();
    }
    if (tid == 0) {
        float s = ss[0], q = sq[0];
        g_stat[0] = s / (float)EE;
        g_stat[1] = rsqrtf((q - s * s / (float)EE) / (float)(EE - 1));
    }
}

// ---------------------------------------------------------------------------
// 2. prez: zero accumulator + precompute ya/yb (node-major), fused
// ---------------------------------------------------------------------------
__global__ void __launch_bounds__(256) k_prez(const float* __restrict__ x,
                                              const float* __restrict__ W1,
                                              const float* __restrict__ b1) {
    int gt = blockIdx.x * blockDim.x + threadIdx.x;
    for (int i = gt; i < BB * NN * 8; i += gridDim.x * blockDim.x)
        g_acc4[i] = make_float4(0.f, 0.f, 0.f, 0.f);

    int lane   = threadIdx.x & 31;
    int warp   = gt >> 5;
    int nwarps = (gridDim.x * blockDim.x) >> 5;

    u64 wab[32];
#pragma unroll
    for (int k = 0; k < 32; k++) {
        wab[k] = pk2(__ldg(&W1[k * 32 + lane]), __ldg(&W1[(32 + k) * 32 + lane]));
    }
    u64 binit = pk2(__ldg(&b1[lane]), 0.f);

    float* ya = reinterpret_cast<float*>(g_ya4);
    float* yb = reinterpret_cast<float*>(g_yb4);

    for (int row = warp; row < BB * NN; row += nwarps) {
        int b = row / NN;
        int n = row - b * NN;
        float xv = __ldg(&x[row * 32 + lane]);
        u64 acc = binit;
#pragma unroll
        for (int k = 0; k < 32; k++) {
            float xk = __shfl_sync(0xffffffffu, xv, k);
            acc = fma2(pk2(xk, xk), wab[k], acc);
        }
        float sa, sb;
        upk2(sa, sb, acc);
        int off = (n * BB + b) * 32 + lane;
        ya[off] = sa;
        yb[off] = sb;
    }
}

// ---------------------------------------------------------------------------
// 3. k_edge (launch index 3 -> profiled). 3-phase hybrid per CTA:
//    P1 warp=edge: coalesced gather -> h1 -> tile.   (R5-cheap part)
//    P2 thread=task: uniform-broadcast W2 LDS matvec. (R4-cheap part)
//    P3 warp=edge: tile -> coalesced signed RED.      (R5-cheap part)
// ---------------------------------------------------------------------------
__global__ void __launch_bounds__(256) k_edge(const void* __restrict__ ei,
                                              const float* __restrict__ ea,
                                              const float* __restrict__ W1,
                                              const float* __restrict__ W2,
                                              const float* __restrict__ b2) {
    __shared__ float      tile[256 * ROWF];   // 36864B: 256 task rows
    __shared__ ulonglong2 w2p[32][8];         // W2[k] padded to 32 floats
    __shared__ ulonglong2 w1cp[8];            // W1 edge-attr row (32 floats)
    __shared__ ulonglong2 b2p[8];             // b2 padded (32 floats)

    int tid = threadIdx.x;
    for (int i = tid; i < 32 * 32; i += 256) {
        int k = i >> 5, j = i & 31;
        reinterpret_cast<float*>(w2p)[k * 32 + j] = (j < 30) ? W2[k * 30 + j] : 0.f;
    }
    if (tid < 32) {
        reinterpret_cast<float*>(w1cp)[tid] = W1[64 * 32 + tid];
        reinterpret_cast<float*>(b2p)[tid]  = (tid < 30) ? b2[tid] : 0.f;
    }
    __syncthreads();

    int lane = tid & 31;
    int wid  = tid >> 5;
    int b    = lane >> 3;
    int f4   = lane & 7;
    int ebase = blockIdx.x * TILE_E + wid * 8;

    float mean = g_stat[0], rstd = g_stat[1];

    // ---- Phase 1: gather + layer 1 -> tile ----
#pragma unroll
    for (int it = 0; it < 8; it++) {
        int e = ebase + it;
        int src, tgt;
        load_edge(ei, e, src, tgt);
        float ean = (__ldg(&ea[e]) - mean) * rstd;
        u64 ean2 = pk2(ean, ean);

        ulonglong2 A = *(reinterpret_cast<const ulonglong2*>(g_ya4) + src * 32 + lane);
        ulonglong2 C = *(reinterpret_cast<const ulonglong2*>(g_yb4) + tgt * 32 + lane);
        ulonglong2 wc = w1cp[f4];
        u64 t0 = fma2(ean2, wc.x, add2(A.x, C.x));
        u64 t1 = fma2(ean2, wc.y, add2(A.y, C.y));
        float v0, v1, v2, v3;
        upk2(v0, v1, t0);
        upk2(v2, v3, t1);
        int task = (wid * 8 + it) * 4 + b;
        *reinterpret_cast<float4*>(&tile[task * ROWF + f4 * 4]) =
            make_float4(sigt(v0), sigt(v1), sigt(v2), sigt(v3));
    }
    __syncthreads();

    // ---- Phase 2: thread = task; W2 via uniform-broadcast LDS ----
    {
        float h[32];
#pragma unroll
        for (int q = 0; q < 8; q++) {
            float4 v = *reinterpret_cast<const float4*>(&tile[tid * ROWF + q * 4]);
            h[4 * q + 0] = v.x; h[4 * q + 1] = v.y;
            h[4 * q + 2] = v.z; h[4 * q + 3] = v.w;
        }

        u64 acc[15];
        const u64* b2f = reinterpret_cast<const u64*>(b2p);
#pragma unroll
        for (int j = 0; j < 15; j++) acc[j] = b2f[j];

#pragma unroll
        for (int k = 0; k < 32; k++) {
            u64 hh = pk2(h[k], h[k]);
#pragma unroll
            for (int q = 0; q < 8; q++) {
                ulonglong2 w = w2p[k][q];          // warp-uniform -> broadcast
                acc[2 * q] = fma2(hh, w.x, acc[2 * q]);
                if (q < 7) acc[2 * q + 1] = fma2(hh, w.y, acc[2 * q + 1]);
            }
        }

        float h2v[32];
#pragma unroll
        for (int j = 0; j < 15; j++) {
            float lo, hi;
            upk2(lo, hi, acc[j]);
            h2v[2 * j]     = sigf(lo);
            h2v[2 * j + 1] = sigf(hi);
        }
        h2v[30] = 0.f; h2v[31] = 0.f;

#pragma unroll
        for (int q = 0; q < 8; q++) {
            *reinterpret_cast<float4*>(&tile[tid * ROWF + q * 4]) =
                make_float4(h2v[4 * q], h2v[4 * q + 1], h2v[4 * q + 2], h2v[4 * q + 3]);
        }
    }
    __syncthreads();

    // ---- Phase 3: tile -> coalesced signed RED scatter ----
#pragma unroll
    for (int it = 0; it < 8; it++) {
        int e = ebase + it;
        int src, tgt;
        load_edge(ei, e, src, tgt);
        int task = (wid * 8 + it) * 4 + b;
        float4 v = *reinterpret_cast<const float4*>(&tile[task * ROWF + f4 * 4]);

        float* at = reinterpret_cast<float*>(g_acc4) + tgt * 128 + lane * 4;
        float* as = reinterpret_cast<float*>(g_acc4) + src * 128 + lane * 4;
        red4(at, v.x, v.y, v.z, v.w);
        red4(as, negf(v.x), negf(v.y), negf(v.z), negf(v.w));
    }
}

// ---------------------------------------------------------------------------
// 4. final: out = sigmoid(acc[:, :30] @ W3 + b3)
// ---------------------------------------------------------------------------
__global__ void __launch_bounds__(256) k_out(const float* __restrict__ W3,
                                             const float* __restrict__ b3,
                                             float* __restrict__ out) {
    int lane   = threadIdx.x & 31;
    int warp   = (blockIdx.x * blockDim.x + threadIdx.x) >> 5;
    int nwarps = (gridDim.x * blockDim.x) >> 5;

    float w3r[30];
#pragma unroll
    for (int k = 0; k < 30; k++) w3r[k] = __ldg(&W3[k * 32 + lane]);
    float bv = __ldg(&b3[lane]);

    const float* accf = reinterpret_cast<const float*>(g_acc4);

    for (int row = warp; row < BB * NN; row += nwarps) {
        int b = row / NN;
        int n = row - b * NN;
        float av = accf[(n * BB + b) * 32 + lane];
        float s = bv;
#pragma unroll
        for (int k = 0; k < 30; k++) {
            s = fmaf(__shfl_sync(0xffffffffu, av, k), w3r[k], s);
        }
        out[row * 32 + lane] = sigf(s);
    }
}

// ---------------------------------------------------------------------------
// launch (k_edge at ncu capture index 3)
// ---------------------------------------------------------------------------
extern "C" void kernel_launch(void* const* d_in, const int* in_sizes, int n_in,
                              void* d_out, int out_size) {
    const float *x = 0, *ea = 0, *W1 = 0, *b1 = 0, *W2 = 0, *b2 = 0, *W3 = 0, *b3 = 0;
    const void* ei = 0;
    int nW = 0, nb = 0;
    for (int i = 0; i < n_in; i++) {
        switch (in_sizes[i]) {
            case 6400000: x  = (const float*)d_in[i]; break;
            case 1600000: ei = d_in[i];               break;
            case 800000:  ea = (const float*)d_in[i]; break;
            case 2080:    W1 = (const float*)d_in[i]; break;
            case 960:     if (nW++ == 0) W2 = (const float*)d_in[i];
                          else           W3 = (const float*)d_in[i]; break;
            case 32:      if (nb++ == 0) b1 = (const float*)d_in[i];
                          else           b3 = (const float*)d_in[i]; break;
            case 30:      b2 = (const float*)d_in[i]; break;
        }
    }
    float* out = (float*)d_out;

    k_stat1<<<256, 256>>>(ea, ei);                    // 0
    k_stat2<<<1, 256>>>();                            // 1
    k_prez<<<512, 256>>>(x, W1, b1);                  // 2
    k_edge<<<EE / TILE_E, 256>>>(ei, ea, W1, W2, b2); // 3  <- profiled
    k_out<<<512, 256>>>(W3, b3, out);                 // 4
}

// round 11
// speedup vs baseline: 2.4037x; 1.1648x over previous
#include <cuda_runtime.h>
#include <cuda_bf16.h>
#include <cstdint>

#define BB 4
#define NN 50000
#define EE 800000
#define TILE_E 64          // edges per CTA (8 per warp)
#define ROWF 36            // tile row stride in floats (div by 4 -> float4-aligned)

__device__ float4 g_ya4[BB * NN * 8];
__device__ float4 g_yb4[BB * NN * 8];
__device__ float4 g_acc4[BB * NN * 8];
__device__ float  g_part[512];
__device__ float  g_stat[2];
__device__ int    g_is64;

typedef unsigned long long u64;

__device__ __forceinline__ u64 pk2(float lo, float hi) {
    u64 r; asm("mov.b64 %0,{%1,%2};" : "=l"(r) : "f"(lo), "f"(hi)); return r;
}
__device__ __forceinline__ void upk2(float& lo, float& hi, u64 v) {
    asm("mov.b64 {%0,%1},%2;" : "=f"(lo), "=f"(hi) : "l"(v));
}
__device__ __forceinline__ u64 fma2(u64 a, u64 b, u64 c) {
    u64 d; asm("fma.rn.f32x2 %0,%1,%2,%3;" : "=l"(d) : "l"(a), "l"(b), "l"(c)); return d;
}
__device__ __forceinline__ u64 add2(u64 a, u64 b) {
    u64 d; asm("add.rn.f32x2 %0,%1,%2;" : "=l"(d) : "l"(a), "l"(b)); return d;
}

__device__ __forceinline__ float sigf(float x) {
    return __fdividef(1.0f, 1.0f + __expf(-x));
}
__device__ __forceinline__ float sigt(float x) {     // fast sigmoid (h1 only)
    float t;
    asm("tanh.approx.f32 %0, %1;" : "=f"(t) : "f"(x * 0.5f));
    return fmaf(0.5f, t, 0.5f);
}
__device__ __forceinline__ float negf(float x) {
    return __int_as_float(__float_as_int(x) ^ 0x80000000);
}
__device__ __forceinline__ void red4(float* p, float a, float b, float c, float d) {
    asm volatile("red.global.add.v4.f32 [%0], {%1,%2,%3,%4};"
                 :: "l"(p), "f"(a), "f"(b), "f"(c), "f"(d) : "memory");
}
__device__ __forceinline__ uint32_t f2tf(float f) {
    uint32_t r; asm("cvt.rna.tf32.f32 %0,%1;" : "=r"(r) : "f"(f)); return r;
}
__device__ __forceinline__ void mma_tf32(float& c0, float& c1, float& c2, float& c3,
                                         uint32_t a0, uint32_t a1, uint32_t a2, uint32_t a3,
                                         uint32_t b0, uint32_t b1) {
    asm("mma.sync.aligned.m16n8k8.row.col.f32.tf32.tf32.f32 "
        "{%0,%1,%2,%3},{%4,%5,%6,%7},{%8,%9},{%0,%1,%2,%3};"
        : "+f"(c0), "+f"(c1), "+f"(c2), "+f"(c3)
        : "r"(a0), "r"(a1), "r"(a2), "r"(a3), "r"(b0), "r"(b1));
}

__device__ __forceinline__ void load_edge(const void* ei, int e, int& src, int& tgt) {
    if (g_is64) {
        const long long* p = (const long long*)ei;
        src = (int)__ldg(&p[e]);
        tgt = (int)__ldg(&p[EE + e]);
    } else {
        const int* p = (const int*)ei;
        src = __ldg(&p[e]);
        tgt = __ldg(&p[EE + e]);
    }
    src = min(max(src, 0), NN - 1);
    tgt = min(max(tgt, 0), NN - 1);
}

// ---------------------------------------------------------------------------
// 0. stats pass 1 + index-width detection
// ---------------------------------------------------------------------------
__global__ void k_stat1(const float* __restrict__ ea, const void* __restrict__ ei) {
    if (blockIdx.x == 0 && threadIdx.x == 0) {
        const long long* p = (const long long*)ei;
        int ok64 = 1;
        for (int j = 0; j < 16; j++) {
            long long v = p[j];
            if (v < 0 || v >= (long long)NN) ok64 = 0;
        }
        g_is64 = ok64;
    }
    __shared__ float ss[256], sq[256];
    int tid = threadIdx.x;
    float s = 0.f, q = 0.f;
    for (int i = blockIdx.x * 256 + tid; i < EE; i += 256 * 256) {
        float v = __ldg(&ea[i]);
        s += v; q += v * v;
    }
    ss[tid] = s; sq[tid] = q;
    __syncthreads();
    for (int o = 128; o > 0; o >>= 1) {
        if (tid < o) { ss[tid] += ss[tid + o]; sq[tid] += sq[tid + o]; }
        __syncthreads();
    }
    if (tid == 0) {
        g_part[blockIdx.x]       = ss[0];
        g_part[256 + blockIdx.x] = sq[0];
    }
}

__global__ void k_stat2() {
    __shared__ float ss[256], sq[256];
    int tid = threadIdx.x;
    ss[tid] = g_part[tid];
    sq[tid] = g_part[256 + tid];
    __syncthreads();
    for (int o = 128; o > 0; o >>= 1) {
        if (tid < o) { ss[tid] += ss[tid + o]; sq[tid] += sq[tid + o]; }
        __syncthreads();
    }
    if (tid == 0) {
        float s = ss[0], q = sq[0];
        g_stat[0] = s / (float)EE;
        g_stat[1] = rsqrtf((q - s * s / (float)EE) / (float)(EE - 1));
    }
}

// ---------------------------------------------------------------------------
// 2. prez: zero accumulator + precompute ya/yb (node-major), fused
// ---------------------------------------------------------------------------
__global__ void __launch_bounds__(256) k_prez(const float* __restrict__ x,
                                              const float* __restrict__ W1,
                                              const float* __restrict__ b1) {
    int gt = blockIdx.x * blockDim.x + threadIdx.x;
    for (int i = gt; i < BB * NN * 8; i += gridDim.x * blockDim.x)
        g_acc4[i] = make_float4(0.f, 0.f, 0.f, 0.f);

    int lane   = threadIdx.x & 31;
    int warp   = gt >> 5;
    int nwarps = (gridDim.x * blockDim.x) >> 5;

    u64 wab[32];
#pragma unroll
    for (int k = 0; k < 32; k++) {
        wab[k] = pk2(__ldg(&W1[k * 32 + lane]), __ldg(&W1[(32 + k) * 32 + lane]));
    }
    u64 binit = pk2(__ldg(&b1[lane]), 0.f);

    float* ya = reinterpret_cast<float*>(g_ya4);
    float* yb = reinterpret_cast<float*>(g_yb4);

    for (int row = warp; row < BB * NN; row += nwarps) {
        int b = row / NN;
        int n = row - b * NN;
        float xv = __ldg(&x[row * 32 + lane]);
        u64 acc = binit;
#pragma unroll
        for (int k = 0; k < 32; k++) {
            float xk = __shfl_sync(0xffffffffu, xv, k);
            acc = fma2(pk2(xk, xk), wab[k], acc);
        }
        float sa, sb;
        upk2(sa, sb, acc);
        int off = (n * BB + b) * 32 + lane;
        ya[off] = sa;
        yb[off] = sb;
    }
}

// ---------------------------------------------------------------------------
// 3. k_edge (launch index 3 -> profiled). Per-warp self-contained:
//    P1 warp=edge: coalesced gather -> h1 -> warp tile (fp32)
//    P2 tf32 mma.sync: [32 tasks x 32] @ W2[32 x 32pad] on tensor pipe;
//       W2 fragments register-resident (loaded once), A from tile (1wf/LDS)
//    P3 warp=edge: tile -> coalesced signed RED (indices cached in regs)
// ---------------------------------------------------------------------------
__global__ void __launch_bounds__(256) k_edge(const void* __restrict__ ei,
                                              const float* __restrict__ ea,
                                              const float* __restrict__ W1,
                                              const float* __restrict__ W2,
                                              const float* __restrict__ b2) {
    __shared__ float      tile[8 * 32 * ROWF];  // per-warp 32-task tiles (36864B)
    __shared__ float      w2t[32 * ROWF];       // W2 transposed [n][k], stride 36
    __shared__ ulonglong2 w1cp[8];              // W1 edge-attr row (32 floats)
    __shared__ float      b2s[32];              // b2 padded

    int tid = threadIdx.x;
    for (int i = tid; i < 32 * ROWF; i += 256) {
        int n = i / ROWF, k = i - n * ROWF;
        w2t[i] = (k < 32 && n < 30) ? W2[k * 30 + n] : 0.f;
    }
    if (tid < 32) {
        reinterpret_cast<float*>(w1cp)[tid] = W1[64 * 32 + tid];
        b2s[tid] = (tid < 30) ? b2[tid] : 0.f;
    }
    __syncthreads();

    int lane = tid & 31;
    int wid  = tid >> 5;
    int b    = lane >> 3;   // batch       (P1/P3 mapping)
    int f4   = lane & 7;    // feature quad
    int g    = lane >> 2;   // mma group id
    int ti   = lane & 3;    // mma thread-in-group
    int ebase = blockIdx.x * TILE_E + wid * 8;

    float* tw = tile + wid * (32 * ROWF);
    float mean = g_stat[0], rstd = g_stat[1];

    int se[8], te[8];

    // ---- Phase 1: gather + layer 1 -> warp tile ----
#pragma unroll
    for (int it = 0; it < 8; it++) {
        int e = ebase + it;
        load_edge(ei, e, se[it], te[it]);
        float ean = (__ldg(&ea[e]) - mean) * rstd;
        u64 ean2 = pk2(ean, ean);

        ulonglong2 A = *(reinterpret_cast<const ulonglong2*>(g_ya4) + se[it] * 32 + lane);
        ulonglong2 C = *(reinterpret_cast<const ulonglong2*>(g_yb4) + te[it] * 32 + lane);
        ulonglong2 wc = w1cp[f4];
        u64 t0 = fma2(ean2, wc.x, add2(A.x, C.x));
        u64 t1 = fma2(ean2, wc.y, add2(A.y, C.y));
        float v0, v1, v2, v3;
        upk2(v0, v1, t0);
        upk2(v2, v3, t1);
        *reinterpret_cast<float4*>(&tw[(it * 4 + b) * ROWF + f4 * 4]) =
            make_float4(sigt(v0), sigt(v1), sigt(v2), sigt(v3));
    }
    __syncwarp();

    // ---- Phase 2: tf32 tensor-core layer 2 ----
    {
        // B fragments: loaded once, conflict-free (bank = 4g+ti + 8kt)
        uint32_t bf[4][4][2];
#pragma unroll
        for (int kt = 0; kt < 4; kt++)
#pragma unroll
            for (int nt = 0; nt < 4; nt++) {
                int n = nt * 8 + g;
                bf[kt][nt][0] = f2tf(w2t[n * ROWF + kt * 8 + ti]);
                bf[kt][nt][1] = f2tf(w2t[n * ROWF + kt * 8 + ti + 4]);
            }

#pragma unroll
        for (int mt = 0; mt < 2; mt++) {
            float c[4][4];
#pragma unroll
            for (int nt = 0; nt < 4; nt++) {
                float blo = b2s[nt * 8 + 2 * ti];
                float bhi = b2s[nt * 8 + 2 * ti + 1];
                c[nt][0] = blo; c[nt][1] = bhi;
                c[nt][2] = blo; c[nt][3] = bhi;
            }
#pragma unroll
            for (int kt = 0; kt < 4; kt++) {
                int r0 = (mt * 16 + g) * ROWF + kt * 8 + ti;
                int r1 = (mt * 16 + g + 8) * ROWF + kt * 8 + ti;
                uint32_t a0 = f2tf(tw[r0]);
                uint32_t a1 = f2tf(tw[r1]);
                uint32_t a2 = f2tf(tw[r0 + 4]);
                uint32_t a3 = f2tf(tw[r1 + 4]);
#pragma unroll
                for (int nt = 0; nt < 4; nt++)
                    mma_tf32(c[nt][0], c[nt][1], c[nt][2], c[nt][3],
                             a0, a1, a2, a3, bf[kt][nt][0], bf[kt][nt][1]);
            }
            // epilogue: sigmoid + store h2 pairs back to tile
#pragma unroll
            for (int nt = 0; nt < 4; nt++) {
                int j0 = nt * 8 + 2 * ti;
                bool pad = (j0 == 30);
                float v0 = pad ? 0.f : sigf(c[nt][0]);
                float v1 = pad ? 0.f : sigf(c[nt][1]);
                float v2 = pad ? 0.f : sigf(c[nt][2]);
                float v3 = pad ? 0.f : sigf(c[nt][3]);
                *reinterpret_cast<float2*>(&tw[(mt * 16 + g) * ROWF + j0])     = make_float2(v0, v1);
                *reinterpret_cast<float2*>(&tw[(mt * 16 + g + 8) * ROWF + j0]) = make_float2(v2, v3);
            }
        }
    }
    __syncwarp();

    // ---- Phase 3: tile -> coalesced signed RED scatter (cached indices) ----
#pragma unroll
    for (int it = 0; it < 8; it++) {
        float4 v = *reinterpret_cast<const float4*>(&tw[(it * 4 + b) * ROWF + f4 * 4]);
        float* at = reinterpret_cast<float*>(g_acc4) + te[it] * 128 + lane * 4;
        float* as = reinterpret_cast<float*>(g_acc4) + se[it] * 128 + lane * 4;
        red4(at, v.x, v.y, v.z, v.w);
        red4(as, negf(v.x), negf(v.y), negf(v.z), negf(v.w));
    }
}

// ---------------------------------------------------------------------------
// 4. final: out = sigmoid(acc[:, :30] @ W3 + b3)
// ---------------------------------------------------------------------------
__global__ void __launch_bounds__(256) k_out(const float* __restrict__ W3,
                                             const float* __restrict__ b3,
                                             float* __restrict__ out) {
    int lane   = threadIdx.x & 31;
    int warp   = (blockIdx.x * blockDim.x + threadIdx.x) >> 5;
    int nwarps = (gridDim.x * blockDim.x) >> 5;

    float w3r[30];
#pragma unroll
    for (int k = 0; k < 30; k++) w3r[k] = __ldg(&W3[k * 32 + lane]);
    float bv = __ldg(&b3[lane]);

    const float* accf = reinterpret_cast<const float*>(g_acc4);

    for (int row = warp; row < BB * NN; row += nwarps) {
        int b = row / NN;
        int n = row - b * NN;
        float av = accf[(n * BB + b) * 32 + lane];
        float s = bv;
#pragma unroll
        for (int k = 0; k < 30; k++) {
            s = fmaf(__shfl_sync(0xffffffffu, av, k), w3r[k], s);
        }
        out[row * 32 + lane] = sigf(s);
    }
}

// ---------------------------------------------------------------------------
// launch (k_edge at ncu capture index 3)
// ---------------------------------------------------------------------------
extern "C" void kernel_launch(void* const* d_in, const int* in_sizes, int n_in,
                              void* d_out, int out_size) {
    const float *x = 0, *ea = 0, *W1 = 0, *b1 = 0, *W2 = 0, *b2 = 0, *W3 = 0, *b3 = 0;
    const void* ei = 0;
    int nW = 0, nb = 0;
    for (int i = 0; i < n_in; i++) {
        switch (in_sizes[i]) {
            case 6400000: x  = (const float*)d_in[i]; break;
            case 1600000: ei = d_in[i];               break;
            case 800000:  ea = (const float*)d_in[i]; break;
            case 2080:    W1 = (const float*)d_in[i]; break;
            case 960:     if (nW++ == 0) W2 = (const float*)d_in[i];
                          else           W3 = (const float*)d_in[i]; break;
            case 32:      if (nb++ == 0) b1 = (const float*)d_in[i];
                          else           b3 = (const float*)d_in[i]; break;
            case 30:      b2 = (const float*)d_in[i]; break;
        }
    }
    float* out = (float*)d_out;

    k_stat1<<<256, 256>>>(ea, ei);                    // 0
    k_stat2<<<1, 256>>>();                            // 1
    k_prez<<<512, 256>>>(x, W1, b1);                  // 2
    k_edge<<<EE / TILE_E, 256>>>(ei, ea, W1, W2, b2); // 3  <- profiled
    k_out<<<512, 256>>>(W3, b3, out);                 // 4
}

// round 12
// speedup vs baseline: 2.7176x; 1.1306x over previous
#include <cuda_runtime.h>
#include <cuda_bf16.h>
#include <cstdint>

#define BB 4
#define NN 50000
#define EE 800000
#define TILE_E 64          // edges per CTA (8 per warp)
#define ROWF 36            // tile row stride in floats (div by 4 -> float4-aligned)

__device__ float4 g_ya4[BB * NN * 8];
__device__ float4 g_yb4[BB * NN * 8];
__device__ float4 g_acc4[BB * NN * 8];
__device__ float  g_part[512];
__device__ float  g_stat[2];
__device__ int    g_is64;

typedef unsigned long long u64;

__device__ __forceinline__ u64 pk2(float lo, float hi) {
    u64 r; asm("mov.b64 %0,{%1,%2};" : "=l"(r) : "f"(lo), "f"(hi)); return r;
}
__device__ __forceinline__ void upk2(float& lo, float& hi, u64 v) {
    asm("mov.b64 {%0,%1},%2;" : "=f"(lo), "=f"(hi) : "l"(v));
}
__device__ __forceinline__ u64 fma2(u64 a, u64 b, u64 c) {
    u64 d; asm("fma.rn.f32x2 %0,%1,%2,%3;" : "=l"(d) : "l"(a), "l"(b), "l"(c)); return d;
}
__device__ __forceinline__ u64 add2(u64 a, u64 b) {
    u64 d; asm("add.rn.f32x2 %0,%1,%2;" : "=l"(d) : "l"(a), "l"(b)); return d;
}

__device__ __forceinline__ float sigf(float x) {
    return __fdividef(1.0f, 1.0f + __expf(-x));
}
__device__ __forceinline__ float sigt(float x) {     // fast sigmoid (h1 only)
    float t;
    asm("tanh.approx.f32 %0, %1;" : "=f"(t) : "f"(x * 0.5f));
    return fmaf(0.5f, t, 0.5f);
}
__device__ __forceinline__ float negf(float x) {
    return __int_as_float(__float_as_int(x) ^ 0x80000000);
}
__device__ __forceinline__ void red4(float* p, float a, float b, float c, float d) {
    asm volatile("red.global.add.v4.f32 [%0], {%1,%2,%3,%4};"
                 :: "l"(p), "f"(a), "f"(b), "f"(c), "f"(d) : "memory");
}
__device__ __forceinline__ uint32_t f2tf(float f) {
    uint32_t r; asm("cvt.rna.tf32.f32 %0,%1;" : "=r"(r) : "f"(f)); return r;
}
__device__ __forceinline__ void mma_tf32(float& c0, float& c1, float& c2, float& c3,
                                         uint32_t a0, uint32_t a1, uint32_t a2, uint32_t a3,
                                         uint32_t b0, uint32_t b1) {
    asm("mma.sync.aligned.m16n8k8.row.col.f32.tf32.tf32.f32 "
        "{%0,%1,%2,%3},{%4,%5,%6,%7},{%8,%9},{%0,%1,%2,%3};"
        : "+f"(c0), "+f"(c1), "+f"(c2), "+f"(c3)
        : "r"(a0), "r"(a1), "r"(a2), "r"(a3), "r"(b0), "r"(b1));
}

__device__ __forceinline__ void load_edge(const void* ei, int e, int& src, int& tgt) {
    if (g_is64) {
        const long long* p = (const long long*)ei;
        src = (int)__ldg(&p[e]);
        tgt = (int)__ldg(&p[EE + e]);
    } else {
        const int* p = (const int*)ei;
        src = __ldg(&p[e]);
        tgt = __ldg(&p[EE + e]);
    }
    src = min(max(src, 0), NN - 1);
    tgt = min(max(tgt, 0), NN - 1);
}

// ---------------------------------------------------------------------------
// 0. stats pass 1 + index-width detection
// ---------------------------------------------------------------------------
__global__ void k_stat1(const float* __restrict__ ea, const void* __restrict__ ei) {
    if (blockIdx.x == 0 && threadIdx.x == 0) {
        const long long* p = (const long long*)ei;
        int ok64 = 1;
        for (int j = 0; j < 16; j++) {
            long long v = p[j];
            if (v < 0 || v >= (long long)NN) ok64 = 0;
        }
        g_is64 = ok64;
    }
    __shared__ float ss[256], sq[256];
    int tid = threadIdx.x;
    float s = 0.f, q = 0.f;
    for (int i = blockIdx.x * 256 + tid; i < EE; i += 256 * 256) {
        float v = __ldg(&ea[i]);
        s += v; q += v * v;
    }
    ss[tid] = s; sq[tid] = q;
    __syncthreads();
    for (int o = 128; o > 0; o >>= 1) {
        if (tid < o) { ss[tid] += ss[tid + o]; sq[tid] += sq[tid + o]; }
        __syncthreads();
    }
    if (tid == 0) {
        g_part[blockIdx.x]       = ss[0];
        g_part[256 + blockIdx.x] = sq[0];
    }
}

__global__ void k_stat2() {
    __shared__ float ss[256], sq[256];
    int tid = threadIdx.x;
    ss[tid] = g_part[tid];
    sq[tid] = g_part[256 + tid];
    __syncthreads();
    for (int o = 128; o > 0; o >>= 1) {
        if (tid < o) { ss[tid] += ss[tid + o]; sq[tid] += sq[tid + o]; }
        __syncthreads();
    }
    if (tid == 0) {
        float s = ss[0], q = sq[0];
        g_stat[0] = s / (float)EE;
        g_stat[1] = rsqrtf((q - s * s / (float)EE) / (float)(EE - 1));
    }
}

// ---------------------------------------------------------------------------
// 2. prez: zero accumulator + precompute ya/yb (node-major), fused
// ---------------------------------------------------------------------------
__global__ void __launch_bounds__(256) k_prez(const float* __restrict__ x,
                                              const float* __restrict__ W1,
                                              const float* __restrict__ b1) {
    int gt = blockIdx.x * blockDim.x + threadIdx.x;
    for (int i = gt; i < BB * NN * 8; i += gridDim.x * blockDim.x)
        g_acc4[i] = make_float4(0.f, 0.f, 0.f, 0.f);

    int lane   = threadIdx.x & 31;
    int warp   = gt >> 5;
    int nwarps = (gridDim.x * blockDim.x) >> 5;

    u64 wab[32];
#pragma unroll
    for (int k = 0; k < 32; k++) {
        wab[k] = pk2(__ldg(&W1[k * 32 + lane]), __ldg(&W1[(32 + k) * 32 + lane]));
    }
    u64 binit = pk2(__ldg(&b1[lane]), 0.f);

    float* ya = reinterpret_cast<float*>(g_ya4);
    float* yb = reinterpret_cast<float*>(g_yb4);

    for (int row = warp; row < BB * NN; row += nwarps) {
        int b = row / NN;
        int n = row - b * NN;
        float xv = __ldg(&x[row * 32 + lane]);
        u64 acc = binit;
#pragma unroll
        for (int k = 0; k < 32; k++) {
            float xk = __shfl_sync(0xffffffffu, xv, k);
            acc = fma2(pk2(xk, xk), wab[k], acc);
        }
        float sa, sb;
        upk2(sa, sb, acc);
        int off = (n * BB + b) * 32 + lane;
        ya[off] = sa;
        yb[off] = sb;
    }
}

// ---------------------------------------------------------------------------
// 3. k_edge (launch index 3 -> profiled). Per-warp self-contained:
//    P1 warp=edge: coalesced gather -> h1 -> warp tile (fp32)
//    P2 tf32 mma.sync on tensor pipe, W2 fragments register-resident
//    P3 warp=edge: tile -> coalesced signed RED (indices reloaded, uniform)
//    __launch_bounds__(256,3): cap regs at 85 -> 3 CTAs/SM (RF = 64K regs)
// ---------------------------------------------------------------------------
__global__ void __launch_bounds__(256, 3) k_edge(const void* __restrict__ ei,
                                                 const float* __restrict__ ea,
                                                 const float* __restrict__ W1,
                                                 const float* __restrict__ W2,
                                                 const float* __restrict__ b2) {
    __shared__ float      tile[8 * 32 * ROWF];  // per-warp 32-task tiles (36864B)
    __shared__ float      w2t[32 * ROWF];       // W2 transposed [n][k], stride 36
    __shared__ ulonglong2 w1cp[8];              // W1 edge-attr row (32 floats)
    __shared__ float      b2s[32];              // b2 padded

    int tid = threadIdx.x;
    for (int i = tid; i < 32 * ROWF; i += 256) {
        int n = i / ROWF, k = i - n * ROWF;
        w2t[i] = (k < 32 && n < 30) ? W2[k * 30 + n] : 0.f;
    }
    if (tid < 32) {
        reinterpret_cast<float*>(w1cp)[tid] = W1[64 * 32 + tid];
        b2s[tid] = (tid < 30) ? b2[tid] : 0.f;
    }
    __syncthreads();

    int lane = tid & 31;
    int wid  = tid >> 5;
    int b    = lane >> 3;   // batch       (P1/P3 mapping)
    int f4   = lane & 7;    // feature quad
    int g    = lane >> 2;   // mma group id
    int ti   = lane & 3;    // mma thread-in-group
    int ebase = blockIdx.x * TILE_E + wid * 8;

    float* tw = tile + wid * (32 * ROWF);
    float mean = g_stat[0], rstd = g_stat[1];

    // ---- Phase 1: gather + layer 1 -> warp tile ----
#pragma unroll
    for (int it = 0; it < 8; it++) {
        int e = ebase + it;
        int src, tgt;
        load_edge(ei, e, src, tgt);
        float ean = (__ldg(&ea[e]) - mean) * rstd;
        u64 ean2 = pk2(ean, ean);

        ulonglong2 A = *(reinterpret_cast<const ulonglong2*>(g_ya4) + src * 32 + lane);
        ulonglong2 C = *(reinterpret_cast<const ulonglong2*>(g_yb4) + tgt * 32 + lane);
        ulonglong2 wc = w1cp[f4];
        u64 t0 = fma2(ean2, wc.x, add2(A.x, C.x));
        u64 t1 = fma2(ean2, wc.y, add2(A.y, C.y));
        float v0, v1, v2, v3;
        upk2(v0, v1, t0);
        upk2(v2, v3, t1);
        *reinterpret_cast<float4*>(&tw[(it * 4 + b) * ROWF + f4 * 4]) =
            make_float4(sigt(v0), sigt(v1), sigt(v2), sigt(v3));
    }
    __syncwarp();

    // ---- Phase 2: tf32 tensor-core layer 2 ----
    {
        // B fragments: loaded once, conflict-free (bank = 4g+ti + 8kt)
        uint32_t bf[4][4][2];
#pragma unroll
        for (int kt = 0; kt < 4; kt++)
#pragma unroll
            for (int nt = 0; nt < 4; nt++) {
                int n = nt * 8 + g;
                bf[kt][nt][0] = f2tf(w2t[n * ROWF + kt * 8 + ti]);
                bf[kt][nt][1] = f2tf(w2t[n * ROWF + kt * 8 + ti + 4]);
            }

#pragma unroll
        for (int mt = 0; mt < 2; mt++) {
            float c[4][4];
#pragma unroll
            for (int nt = 0; nt < 4; nt++) {
                float blo = b2s[nt * 8 + 2 * ti];
                float bhi = b2s[nt * 8 + 2 * ti + 1];
                c[nt][0] = blo; c[nt][1] = bhi;
                c[nt][2] = blo; c[nt][3] = bhi;
            }
#pragma unroll
            for (int kt = 0; kt < 4; kt++) {
                int r0 = (mt * 16 + g) * ROWF + kt * 8 + ti;
                int r1 = (mt * 16 + g + 8) * ROWF + kt * 8 + ti;
                uint32_t a0 = f2tf(tw[r0]);
                uint32_t a1 = f2tf(tw[r1]);
                uint32_t a2 = f2tf(tw[r0 + 4]);
                uint32_t a3 = f2tf(tw[r1 + 4]);
#pragma unroll
                for (int nt = 0; nt < 4; nt++)
                    mma_tf32(c[nt][0], c[nt][1], c[nt][2], c[nt][3],
                             a0, a1, a2, a3, bf[kt][nt][0], bf[kt][nt][1]);
            }
            // epilogue: sigmoid + store h2 pairs back to tile
#pragma unroll
            for (int nt = 0; nt < 4; nt++) {
                int j0 = nt * 8 + 2 * ti;
                bool pad = (j0 == 30);
                float v0 = pad ? 0.f : sigf(c[nt][0]);
                float v1 = pad ? 0.f : sigf(c[nt][1]);
                float v2 = pad ? 0.f : sigf(c[nt][2]);
                float v3 = pad ? 0.f : sigf(c[nt][3]);
                *reinterpret_cast<float2*>(&tw[(mt * 16 + g) * ROWF + j0])     = make_float2(v0, v1);
                *reinterpret_cast<float2*>(&tw[(mt * 16 + g + 8) * ROWF + j0]) = make_float2(v2, v3);
            }
        }
    }
    __syncwarp();

    // ---- Phase 3: tile -> coalesced signed RED scatter ----
    // indices reloaded (warp-uniform LDG -> 1 wavefront each; cheaper than
    // holding 16 registers across the whole kernel)
#pragma unroll
    for (int it = 0; it < 8; it++) {
        int e = ebase + it;
        int src, tgt;
        load_edge(ei, e, src, tgt);
        float4 v = *reinterpret_cast<const float4*>(&tw[(it * 4 + b) * ROWF + f4 * 4]);
        float* at = reinterpret_cast<float*>(g_acc4) + tgt * 128 + lane * 4;
        float* as = reinterpret_cast<float*>(g_acc4) + src * 128 + lane * 4;
        red4(at, v.x, v.y, v.z, v.w);
        red4(as, negf(v.x), negf(v.y), negf(v.z), negf(v.w));
    }
}

// ---------------------------------------------------------------------------
// 4. final: out = sigmoid(acc[:, :30] @ W3 + b3)
// ---------------------------------------------------------------------------
__global__ void __launch_bounds__(256) k_out(const float* __restrict__ W3,
                                             const float* __restrict__ b3,
                                             float* __restrict__ out) {
    int lane   = threadIdx.x & 31;
    int warp   = (blockIdx.x * blockDim.x + threadIdx.x) >> 5;
    int nwarps = (gridDim.x * blockDim.x) >> 5;

    float w3r[30];
#pragma unroll
    for (int k = 0; k < 30; k++) w3r[k] = __ldg(&W3[k * 32 + lane]);
    float bv = __ldg(&b3[lane]);

    const float* accf = reinterpret_cast<const float*>(g_acc4);

    for (int row = warp; row < BB * NN; row += nwarps) {
        int b = row / NN;
        int n = row - b * NN;
        float av = accf[(n * BB + b) * 32 + lane];
        float s = bv;
#pragma unroll
        for (int k = 0; k < 30; k++) {
            s = fmaf(__shfl_sync(0xffffffffu, av, k), w3r[k], s);
        }
        out[row * 32 + lane] = sigf(s);
    }
}

// ---------------------------------------------------------------------------
// launch (k_edge at ncu capture index 3)
// ---------------------------------------------------------------------------
extern "C" void kernel_launch(void* const* d_in, const int* in_sizes, int n_in,
                              void* d_out, int out_size) {
    const float *x = 0, *ea = 0, *W1 = 0, *b1 = 0, *W2 = 0, *b2 = 0, *W3 = 0, *b3 = 0;
    const void* ei = 0;
    int nW = 0, nb = 0;
    for (int i = 0; i < n_in; i++) {
        switch (in_sizes[i]) {
            case 6400000: x  = (const float*)d_in[i]; break;
            case 1600000: ei = d_in[i];               break;
            case 800000:  ea = (const float*)d_in[i]; break;
            case 2080:    W1 = (const float*)d_in[i]; break;
            case 960:     if (nW++ == 0) W2 = (const float*)d_in[i];
                          else           W3 = (const float*)d_in[i]; break;
            case 32:      if (nb++ == 0) b1 = (const float*)d_in[i];
                          else           b3 = (const float*)d_in[i]; break;
            case 30:      b2 = (const float*)d_in[i]; break;
        }
    }
    float* out = (float*)d_out;

    k_stat1<<<256, 256>>>(ea, ei);                    // 0
    k_stat2<<<1, 256>>>();                            // 1
    k_prez<<<512, 256>>>(x, W1, b1);                  // 2
    k_edge<<<EE / TILE_E, 256>>>(ei, ea, W1, W2, b2); // 3  <- profiled
    k_out<<<512, 256>>>(W3, b3, out);                 // 4
}

// round 15
// speedup vs baseline: 3.2660x; 1.2018x over previous
#include <cuda_runtime.h>
#include <cuda_fp16.h>
#include <cstdint>

#define BB 4
#define NN 50000
#define EE 800000
#define TILE_E 64          // edges per CTA (8 per warp)
#define ROWH 40            // fp16 tile row stride (80B; conflict-free mma reads)

__device__ __half  g_yah[BB * NN * 32];  // ya fp16, node-major (n*4+b)*32+f
__device__ __half  g_ybh[BB * NN * 32];  // yb fp16
__device__ float4  g_acc4[BB * NN * 8];  // fp32 accumulator
__device__ float   g_part[512];
__device__ float   g_stat[2];
__device__ int     g_is64;

typedef unsigned long long u64;

__device__ __forceinline__ u64 pk2(float lo, float hi) {
    u64 r; asm("mov.b64 %0,{%1,%2};" : "=l"(r) : "f"(lo), "f"(hi)); return r;
}
__device__ __forceinline__ void upk2(float& lo, float& hi, u64 v) {
    asm("mov.b64 {%0,%1},%2;" : "=f"(lo), "=f"(hi) : "l"(v));
}
__device__ __forceinline__ u64 fma2(u64 a, u64 b, u64 c) {
    u64 d; asm("fma.rn.f32x2 %0,%1,%2,%3;" : "=l"(d) : "l"(a), "l"(b), "l"(c)); return d;
}

__device__ __forceinline__ float sigf(float x) {
    return __fdividef(1.0f, 1.0f + __expf(-x));
}
__device__ __forceinline__ float sigt(float x) {     // fast sigmoid (h1 only)
    float t;
    asm("tanh.approx.f32 %0, %1;" : "=f"(t) : "f"(x * 0.5f));
    return fmaf(0.5f, t, 0.5f);
}
__device__ __forceinline__ float negf(float x) {
    return __int_as_float(__float_as_int(x) ^ 0x80000000);
}
__device__ __forceinline__ void red4(float* p, float a, float b, float c, float d) {
    asm volatile("red.global.add.v4.f32 [%0], {%1,%2,%3,%4};"
                 :: "l"(p), "f"(a), "f"(b), "f"(c), "f"(d) : "memory");
}
__device__ __forceinline__ uint32_t pkh(float lo, float hi) {
    __half2 p = __floats2half2_rn(lo, hi);
    return *reinterpret_cast<uint32_t*>(&p);
}
__device__ __forceinline__ float2 uph(uint32_t v) {
    return __half22float2(*reinterpret_cast<__half2*>(&v));
}
__device__ __forceinline__ void mma_f16(float& c0, float& c1, float& c2, float& c3,
                                        uint32_t a0, uint32_t a1, uint32_t a2, uint32_t a3,
                                        uint32_t b0, uint32_t b1) {
    asm("mma.sync.aligned.m16n8k16.row.col.f32.f16.f16.f32 "
        "{%0,%1,%2,%3},{%4,%5,%6,%7},{%8,%9},{%0,%1,%2,%3};"
        : "+f"(c0), "+f"(c1), "+f"(c2), "+f"(c3)
        : "r"(a0), "r"(a1), "r"(a2), "r"(a3), "r"(b0), "r"(b1));
}

__device__ __forceinline__ void load_edge(const void* ei, int e, int& src, int& tgt) {
    if (g_is64) {
        const long long* p = (const long long*)ei;
        src = (int)__ldg(&p[e]);
        tgt = (int)__ldg(&p[EE + e]);
    } else {
        const int* p = (const int*)ei;
        src = __ldg(&p[e]);
        tgt = __ldg(&p[EE + e]);
    }
    src = min(max(src, 0), NN - 1);
    tgt = min(max(tgt, 0), NN - 1);
}

// ---------------------------------------------------------------------------
// 0. stats pass 1 + index-width detection
// ---------------------------------------------------------------------------
__global__ void k_stat1(const float* __restrict__ ea, const void* __restrict__ ei) {
    if (blockIdx.x == 0 && threadIdx.x == 0) {
        const long long* p = (const long long*)ei;
        int ok64 = 1;
        for (int j = 0; j < 16; j++) {
            long long v = p[j];
            if (v < 0 || v >= (long long)NN) ok64 = 0;
        }
        g_is64 = ok64;
    }
    __shared__ float ss[256], sq[256];
    int tid = threadIdx.x;
    float s = 0.f, q = 0.f;
    for (int i = blockIdx.x * 256 + tid; i < EE; i += 256 * 256) {
        float v = __ldg(&ea[i]);
        s += v; q += v * v;
    }
    ss[tid] = s; sq[tid] = q;
    __syncthreads();
    for (int o = 128; o > 0; o >>= 1) {
        if (tid < o) { ss[tid] += ss[tid + o]; sq[tid] += sq[tid + o]; }
        __syncthreads();
    }
    if (tid == 0) {
        g_part[blockIdx.x]       = ss[0];
        g_part[256 + blockIdx.x] = sq[0];
    }
}

__global__ void k_stat2() {
    __shared__ float ss[256], sq[256];
    int tid = threadIdx.x;
    ss[tid] = g_part[tid];
    sq[tid] = g_part[256 + tid];
    __syncthreads();
    for (int o = 128; o > 0; o >>= 1) {
        if (tid < o) { ss[tid] += ss[tid + o]; sq[tid] += sq[tid + o]; }
        __syncthreads();
    }
    if (tid == 0) {
        float s = ss[0], q = sq[0];
        g_stat[0] = s / (float)EE;
        g_stat[1] = rsqrtf((q - s * s / (float)EE) / (float)(EE - 1));
    }
}

// ---------------------------------------------------------------------------
// 2. prez: zero accumulator + precompute ya/yb (fp16, node-major), fused
// ---------------------------------------------------------------------------
__global__ void __launch_bounds__(256) k_prez(const float* __restrict__ x,
                                              const float* __restrict__ W1,
                                              const float* __restrict__ b1) {
    int gt = blockIdx.x * blockDim.x + threadIdx.x;
    for (int i = gt; i < BB * NN * 8; i += gridDim.x * blockDim.x)
        g_acc4[i] = make_float4(0.f, 0.f, 0.f, 0.f);

    int lane   = threadIdx.x & 31;
    int warp   = gt >> 5;
    int nwarps = (gridDim.x * blockDim.x) >> 5;

    u64 wab[32];
#pragma unroll
    for (int k = 0; k < 32; k++) {
        wab[k] = pk2(__ldg(&W1[k * 32 + lane]), __ldg(&W1[(32 + k) * 32 + lane]));
    }
    u64 binit = pk2(__ldg(&b1[lane]), 0.f);

    for (int row = warp; row < BB * NN; row += nwarps) {
        int b = row / NN;
        int n = row - b * NN;
        float xv = __ldg(&x[row * 32 + lane]);
        u64 acc = binit;
#pragma unroll
        for (int k = 0; k < 32; k++) {
            float xk = __shfl_sync(0xffffffffu, xv, k);
            acc = fma2(pk2(xk, xk), wab[k], acc);
        }
        float sa, sb;
        upk2(sa, sb, acc);
        int off = (n * BB + b) * 32 + lane;
        g_yah[off] = __float2half_rn(sa);
        g_ybh[off] = __float2half_rn(sb);
    }
}

// ---------------------------------------------------------------------------
// 3. k_edge (launch index 3 -> profiled). fp16 pipeline:
//    P1 warp=edge: 256B coalesced fp16 gathers -> fp32 h1 -> fp16 tile
//    P2 mma.m16n8k16.f16 (fp32 accum): W2 fragments register-resident
//    P3 warp=edge: fp16 tile -> fp32 -> coalesced signed RED
// ---------------------------------------------------------------------------
__global__ void __launch_bounds__(256, 4) k_edge(const void* __restrict__ ei,
                                                 const float* __restrict__ ea,
                                                 const float* __restrict__ W1,
                                                 const float* __restrict__ W2,
                                                 const float* __restrict__ b2) {
    __shared__ __half tile[8][32 * ROWH];  // per-warp 32x32 task tiles (20KB)
    __shared__ __half w2h[32 * ROWH];      // W2 [n][k] fp16, stride 40 (2.5KB)
    __shared__ float  w1cs[32];            // W1 edge-attr row fp32
    __shared__ float  b2s[32];             // b2 padded fp32

    int tid = threadIdx.x;
    for (int i = tid; i < 32 * ROWH; i += 256) {
        int n = i / ROWH, k = i - n * ROWH;
        w2h[i] = __float2half_rn((k < 32 && n < 30) ? W2[k * 30 + n] : 0.f);
    }
    if (tid < 32) {
        w1cs[tid] = W1[64 * 32 + tid];
        b2s[tid]  = (tid < 30) ? b2[tid] : 0.f;
    }
    __syncthreads();

    int lane = tid & 31;
    int wid  = tid >> 5;
    int b    = lane >> 3;   // batch       (P1/P3 mapping)
    int f4   = lane & 7;    // feature quad
    int g    = lane >> 2;   // mma group id
    int ti   = lane & 3;    // mma thread-in-group
    int ebase = blockIdx.x * TILE_E + wid * 8;

    __half* tw = tile[wid];
    float mean = g_stat[0], rstd = g_stat[1];

    // ---- Phase 1: fp16 gather + fp32 layer 1 -> fp16 tile ----
    float4 wc4 = *reinterpret_cast<const float4*>(&w1cs[f4 * 4]);
#pragma unroll
    for (int it = 0; it < 8; it++) {
        int e = ebase + it;
        int src, tgt;
        load_edge(ei, e, src, tgt);
        float ean = (__ldg(&ea[e]) - mean) * rstd;

        uint2 Au = *(reinterpret_cast<const uint2*>(g_yah) + src * 32 + lane);
        uint2 Cu = *(reinterpret_cast<const uint2*>(g_ybh) + tgt * 32 + lane);
        float2 a01 = uph(Au.x), a23 = uph(Au.y);
        float2 c01 = uph(Cu.x), c23 = uph(Cu.y);

        float h0 = sigt(fmaf(ean, wc4.x, a01.x + c01.x));
        float h1 = sigt(fmaf(ean, wc4.y, a01.y + c01.y));
        float h2 = sigt(fmaf(ean, wc4.z, a23.x + c23.x));
        float h3 = sigt(fmaf(ean, wc4.w, a23.y + c23.y));

        int task = it * 4 + b;
        uint2 st; st.x = pkh(h0, h1); st.y = pkh(h2, h3);
        *reinterpret_cast<uint2*>(&tw[task * ROWH + f4 * 4]) = st;
    }
    __syncwarp();

    // ---- Phase 2: fp16 tensor-core layer 2 (m16n8k16, fp32 accum) ----
    {
        // B fragments: loaded once, conflict-free; 16 regs total
        uint32_t bf[2][4][2];
#pragma unroll
        for (int kt = 0; kt < 2; kt++)
#pragma unroll
            for (int nt = 0; nt < 4; nt++) {
                int n = nt * 8 + g;
                bf[kt][nt][0] = *reinterpret_cast<const uint32_t*>(&w2h[n * ROWH + kt * 16 + 2 * ti]);
                bf[kt][nt][1] = *reinterpret_cast<const uint32_t*>(&w2h[n * ROWH + kt * 16 + 2 * ti + 8]);
            }

#pragma unroll
        for (int mt = 0; mt < 2; mt++) {
            int m0 = mt * 16 + g;
            int m1 = m0 + 8;
            float c[4][4];
#pragma unroll
            for (int nt = 0; nt < 4; nt++) {
                float blo = b2s[nt * 8 + 2 * ti];
                float bhi = b2s[nt * 8 + 2 * ti + 1];
                c[nt][0] = blo; c[nt][1] = bhi;
                c[nt][2] = blo; c[nt][3] = bhi;
            }
#pragma unroll
            for (int kt = 0; kt < 2; kt++) {
                uint32_t a0 = *reinterpret_cast<const uint32_t*>(&tw[m0 * ROWH + kt * 16 + 2 * ti]);
                uint32_t a1 = *reinterpret_cast<const uint32_t*>(&tw[m1 * ROWH + kt * 16 + 2 * ti]);
                uint32_t a2 = *reinterpret_cast<const uint32_t*>(&tw[m0 * ROWH + kt * 16 + 2 * ti + 8]);
                uint32_t a3 = *reinterpret_cast<const uint32_t*>(&tw[m1 * ROWH + kt * 16 + 2 * ti + 8]);
#pragma unroll
                for (int nt = 0; nt < 4; nt++)
                    mma_f16(c[nt][0], c[nt][1], c[nt][2], c[nt][3],
                            a0, a1, a2, a3, bf[kt][nt][0], bf[kt][nt][1]);
            }
            // epilogue: sigmoid (fp32) -> fp16 pairs back to tile
#pragma unroll
            for (int nt = 0; nt < 4; nt++) {
                int j0 = nt * 8 + 2 * ti;
                bool pad = (j0 == 30);
                float v0 = pad ? 0.f : sigf(c[nt][0]);
                float v1 = pad ? 0.f : sigf(c[nt][1]);
                float v2 = pad ? 0.f : sigf(c[nt][2]);
                float v3 = pad ? 0.f : sigf(c[nt][3]);
                *reinterpret_cast<uint32_t*>(&tw[m0 * ROWH + j0]) = pkh(v0, v1);
                *reinterpret_cast<uint32_t*>(&tw[m1 * ROWH + j0]) = pkh(v2, v3);
            }
        }
    }
    __syncwarp();

    // ---- Phase 3: fp16 tile -> fp32 -> coalesced signed RED scatter ----
#pragma unroll
    for (int it = 0; it < 8; it++) {
        int e = ebase + it;
        int src, tgt;
        load_edge(ei, e, src, tgt);
        int task = it * 4 + b;
        uint2 u = *reinterpret_cast<const uint2*>(&tw[task * ROWH + f4 * 4]);
        float2 v01 = uph(u.x), v23 = uph(u.y);

        float* at = reinterpret_cast<float*>(g_acc4) + tgt * 128 + lane * 4;
        float* as = reinterpret_cast<float*>(g_acc4) + src * 128 + lane * 4;
        red4(at, v01.x, v01.y, v23.x, v23.y);
        red4(as, negf(v01.x), negf(v01.y), negf(v23.x), negf(v23.y));
    }
}

// ---------------------------------------------------------------------------
// 4. final: out = sigmoid(acc[:, :30] @ W3 + b3)
// ---------------------------------------------------------------------------
__global__ void __launch_bounds__(256) k_out(const float* __restrict__ W3,
                                             const float* __restrict__ b3,
                                             float* __restrict__ out) {
    int lane   = threadIdx.x & 31;
    int warp   = (blockIdx.x * blockDim.x + threadIdx.x) >> 5;
    int nwarps = (gridDim.x * blockDim.x) >> 5;

    float w3r[30];
#pragma unroll
    for (int k = 0; k < 30; k++) w3r[k] = __ldg(&W3[k * 32 + lane]);
    float bv = __ldg(&b3[lane]);

    const float* accf = reinterpret_cast<const float*>(g_acc4);

    for (int row = warp; row < BB * NN; row += nwarps) {
        int b = row / NN;
        int n = row - b * NN;
        float av = accf[(n * BB + b) * 32 + lane];
        float s = bv;
#pragma unroll
        for (int k = 0; k < 30; k++) {
            s = fmaf(__shfl_sync(0xffffffffu, av, k), w3r[k], s);
        }
        out[row * 32 + lane] = sigf(s);
    }
}

// ---------------------------------------------------------------------------
// launch (k_edge at ncu capture index 3)
// ---------------------------------------------------------------------------
extern "C" void kernel_launch(void* const* d_in, const int* in_sizes, int n_in,
                              void* d_out, int out_size) {
    const float *x = 0, *ea = 0, *W1 = 0, *b1 = 0, *W2 = 0, *b2 = 0, *W3 = 0, *b3 = 0;
    const void* ei = 0;
    int nW = 0, nb = 0;
    for (int i = 0; i < n_in; i++) {
        switch (in_sizes[i]) {
            case 6400000: x  = (const float*)d_in[i]; break;
            case 1600000: ei = d_in[i];               break;
            case 800000:  ea = (const float*)d_in[i]; break;
            case 2080:    W1 = (const float*)d_in[i]; break;
            case 960:     if (nW++ == 0) W2 = (const float*)d_in[i];
                          else           W3 = (const float*)d_in[i]; break;
            case 32:      if (nb++ == 0) b1 = (const float*)d_in[i];
                          else           b3 = (const float*)d_in[i]; break;
            case 30:      b2 = (const float*)d_in[i]; break;
        }
    }
    float* out = (float*)d_out;

    k_stat1<<<256, 256>>>(ea, ei);                    // 0
    k_stat2<<<1, 256>>>();                            // 1
    k_prez<<<512, 256>>>(x, W1, b1);                  // 2
    k_edge<<<EE / TILE_E, 256>>>(ei, ea, W1, W2, b2); // 3  <- profiled
    k_out<<<512, 256>>>(W3, b3, out);                 // 4
}